// round 1
// baseline (speedup 1.0000x reference)
#include <cuda_runtime.h>
#include <math.h>

// EpochedFutureFill: y[b,t] = sum_s filt[s] * x[b,t-s], via 65536-pt FFT conv.
// 65536 = 256 x 256 four-step FFT. Row pairs packed as complex (Hermitian W
// commutes with packing, so no spectrum unpacking is needed).

#define T_LEN 32768
#define NFFT  65536
#define NPAIRS 128
#define NC 16
#define PAD 17
#define PI_F 3.14159265358979323846f

#define BUFSZ (256*PAD)                       // 4352 float2 per buffer
#define SMEM_FLOAT2 (2*BUFSZ + 256)           // A, B, twiddle table (255 used)
#define SMEM_BYTES (SMEM_FLOAT2 * sizeof(float2))   // 71680 bytes

// 64MB scratch for the 128 packed rows' spectra (P2 runs in place on it).
__device__ float2 g_G[(size_t)NPAIRS * NFFT];
__device__ float2 g_Gf[NFFT];   // filter intermediate
__device__ float2 g_W[NFFT];    // filter spectrum, layout [k1][k2] (transposed)

__device__ __forceinline__ float2 cmul(float2 a, float2 b) {
    return make_float2(a.x*b.x - a.y*b.y, a.x*b.y + a.y*b.x);
}

// Stage twiddle table for radix-4 Stockham, forward sign (e^{-i th}).
// Layout: [0..84]=w1, [85..169]=w2, [170..254]=w3.
// Stage offsets: stage0 (nn=256): p=0..63 at 0; stage1 (nn=64): 64+p;
// stage2 (nn=16): 80+p; stage3 (nn=4): 84.
__device__ void init_twiddles(float2* tw) {
    int t = threadIdx.x;
    if (t < 85) {
        int p, nn;
        if (t < 64)      { p = t;      nn = 256; }
        else if (t < 80) { p = t - 64; nn = 64; }
        else if (t < 84) { p = t - 80; nn = 16; }
        else             { p = 0;      nn = 4; }
        float th = -2.0f * PI_F * (float)p / (float)nn;
        float s1, c1, s2, c2, s3, c3;
        sincosf(th,      &s1, &c1);
        sincosf(2.0f*th, &s2, &c2);
        sincosf(3.0f*th, &s3, &c3);
        tw[t]       = make_float2(c1, s1);
        tw[85 + t]  = make_float2(c2, s2);
        tw[170 + t] = make_float2(c3, s3);
    }
}

// 256-pt Stockham radix-4 FFT over the first smem index, NC parallel columns.
// SIGN=-1 forward, SIGN=+1 (unnormalized) inverse. Natural-order output.
// Result ends in bufA. Begins each stage with a barrier (covers prior writes).
template<int SIGN>
__device__ void fft256(float2* bufA, float2* bufB, const float2* tw) {
    float2* src = bufA;
    float2* dst = bufB;
    const int tid = threadIdx.x;
#pragma unroll
    for (int stg = 0; stg < 4; ++stg) {
        const int sh = 2*stg;
        const int s  = 1 << sh;      // 1,4,16,64
        const int m  = 64 >> sh;     // 64,16,4,1
        const int toff = (stg==0) ? 0 : (stg==1) ? 64 : (stg==2) ? 80 : 84;
        __syncthreads();
#pragma unroll
        for (int it = 0; it < 4; ++it) {
            int item = tid + 256*it;         // 0..1023
            int col  = item & (NC-1);
            int idx  = item >> 4;            // 0..63
            int p = idx >> sh;               // idx / s
            int q = idx & (s-1);             // idx % s
            float2 a = src[(q + s*p)      *PAD + col];
            float2 b = src[(q + s*(p+m))  *PAD + col];
            float2 c = src[(q + s*(p+2*m))*PAD + col];
            float2 d = src[(q + s*(p+3*m))*PAD + col];
            float2 w1 = tw[toff+p], w2 = tw[85+toff+p], w3 = tw[170+toff+p];
            if (SIGN > 0) { w1.y = -w1.y; w2.y = -w2.y; w3.y = -w3.y; }
            float2 apc = make_float2(a.x+c.x, a.y+c.y);
            float2 amc = make_float2(a.x-c.x, a.y-c.y);
            float2 bpd = make_float2(b.x+d.x, b.y+d.y);
            float2 bmd = make_float2(b.x-d.x, b.y-d.y);
            float2 t1, t3;
            if (SIGN < 0) {   // forward: y1 = amc - i*bmd, y3 = amc + i*bmd
                t1 = make_float2(amc.x + bmd.y, amc.y - bmd.x);
                t3 = make_float2(amc.x - bmd.y, amc.y + bmd.x);
            } else {          // inverse: swapped
                t1 = make_float2(amc.x - bmd.y, amc.y + bmd.x);
                t3 = make_float2(amc.x + bmd.y, amc.y - bmd.x);
            }
            int ob = q + s*4*p;
            dst[(ob    )*PAD + col] = make_float2(apc.x+bpd.x, apc.y+bpd.y);
            dst[(ob+  s)*PAD + col] = cmul(w1, t1);
            dst[(ob+2*s)*PAD + col] = cmul(w2, make_float2(apc.x-bpd.x, apc.y-bpd.y));
            dst[(ob+3*s)*PAD + col] = cmul(w3, t3);
        }
        float2* tmpp = src; src = dst; dst = tmpp;
    }
    __syncthreads();   // 4 stages -> result back in bufA
}

// ---------------- Pass 1: forward column FFTs + outer twiddle -----------------
// Input sequence index j = 256*j1 + j2. FFT over j1 for columns j2 in this tile.
// Nonzero only for j1 < 128 (T = L = 32768). Store G[k1][j2] * w^{j2*k1}.
__device__ void fwd_cols_body(const float* row0, const float* row1,
                              float2* gout, int tile) {
    extern __shared__ float2 smem[];
    float2* bufA = smem;
    float2* bufB = smem + BUFSZ;
    float2* tw   = smem + 2*BUFSZ;
    init_twiddles(tw);
    const int tid   = threadIdx.x;
    const int c     = tid & (NC-1);
    const int j2    = tile*NC + c;
    const int rbase = tid >> 4;
#pragma unroll
    for (int it = 0; it < 16; ++it) {
        int j1 = rbase + 16*it;
        float re = 0.f, im = 0.f;
        if (j1 < 128) {
            int j = j1*256 + j2;
            re = row0[j];
            if (row1) im = row1[j];
        }
        bufA[j1*PAD + c] = make_float2(re, im);
    }
    fft256<-1>(bufA, bufB, tw);
    // outer twiddle exp(-2pi i * j2*k1 / 65536), chained per thread
    float2 f, stp;
    {
        float a0 = -2.0f*PI_F * (float)((j2 * rbase) & (NFFT-1)) / (float)NFFT;
        float as = -2.0f*PI_F * (float)((j2 * 16)    & (NFFT-1)) / (float)NFFT;
        float s0, c0, s1, c1;
        sincosf(a0, &s0, &c0); sincosf(as, &s1, &c1);
        f = make_float2(c0, s0); stp = make_float2(c1, s1);
    }
#pragma unroll
    for (int it = 0; it < 16; ++it) {
        int k1 = rbase + 16*it;
        gout[k1*256 + j2] = cmul(bufA[k1*PAD + c], f);
        f = cmul(f, stp);
    }
}

__global__ void __launch_bounds__(256) k_fwd_cols_batch(const float* __restrict__ x) {
    int pr = blockIdx.y;
    const float* r0 = x + (size_t)(2*pr)*T_LEN;
    fwd_cols_body(r0, r0 + T_LEN, g_G + (size_t)pr*NFFT, blockIdx.x);
}

__global__ void __launch_bounds__(256) k_fwd_cols_filt(const float* __restrict__ flt) {
    fwd_cols_body(flt, (const float*)0, g_Gf, blockIdx.x);
}

// ---------------- Filter pass 2: row FFTs -> W in [k1][k2] layout -------------
__global__ void __launch_bounds__(256) k_rows_filt() {
    extern __shared__ float2 smem[];
    float2* bufA = smem; float2* bufB = smem + BUFSZ; float2* tw = smem + 2*BUFSZ;
    init_twiddles(tw);
    const int tid = threadIdx.x;
    const int tile = blockIdx.x;
#pragma unroll
    for (int it = 0; it < 16; ++it) {
        int e = tid + 256*it;
        int r = e >> 8, j2 = e & 255;
        bufA[j2*PAD + r] = g_Gf[(tile*NC + r)*256 + j2];
    }
    fft256<-1>(bufA, bufB, tw);
#pragma unroll
    for (int it = 0; it < 16; ++it) {
        int e = tid + 256*it;
        int r = e >> 8, k2 = e & 255;
        g_W[(tile*NC + r)*256 + k2] = bufA[k2*PAD + r];
    }
}

// ---------- Pass 2: finish forward, multiply W, start inverse (in place) ------
__global__ void __launch_bounds__(256) k_rows_conv() {
    extern __shared__ float2 smem[];
    float2* bufA = smem; float2* bufB = smem + BUFSZ; float2* tw = smem + 2*BUFSZ;
    init_twiddles(tw);
    const int tid  = threadIdx.x;
    const int tile = blockIdx.x;
    float2* g = g_G + (size_t)blockIdx.y * NFFT;
#pragma unroll
    for (int it = 0; it < 16; ++it) {
        int e = tid + 256*it;
        int r = e >> 8, j2 = e & 255;
        bufA[j2*PAD + r] = g[(tile*NC + r)*256 + j2];
    }
    fft256<-1>(bufA, bufB, tw);            // Z[k2] for rows k1 = tile*16 + r
    // pointwise multiply by W[k] = g_W[k1*256 + k2]
#pragma unroll
    for (int it = 0; it < 16; ++it) {
        int e = tid + 256*it;
        int r = e >> 8, k2 = e & 255;
        int idx = k2*PAD + r;
        bufA[idx] = cmul(bufA[idx], g_W[(tile*NC + r)*256 + k2]);
    }
    fft256<1>(bufA, bufB, tw);             // D[j1]  (barrier at stage0 covers writes)
    // inverse outer twiddle exp(+2pi i * k1*j1 / 65536), stage via bufB
    const int r  = tid & (NC-1);
    const int k1 = tile*NC + r;
    const int jb = tid >> 4;
    float2 f, stp;
    {
        float a0 = 2.0f*PI_F * (float)((k1 * jb) & (NFFT-1)) / (float)NFFT;
        float as = 2.0f*PI_F * (float)((k1 * 16) & (NFFT-1)) / (float)NFFT;
        float s0, c0, s1, c1;
        sincosf(a0, &s0, &c0); sincosf(as, &s1, &c1);
        f = make_float2(c0, s0); stp = make_float2(c1, s1);
    }
#pragma unroll
    for (int it = 0; it < 16; ++it) {
        int j1 = jb + 16*it;
        bufB[j1*PAD + r] = cmul(bufA[j1*PAD + r], f);
        f = cmul(f, stp);
    }
    __syncthreads();
#pragma unroll
    for (int it = 0; it < 16; ++it) {
        int e = tid + 256*it;
        int rr = e >> 8, j1 = e & 255;
        g[(tile*NC + rr)*256 + j1] = bufB[j1*PAD + rr];
    }
}

// ---------------- Pass 3: inverse column FFTs + output ------------------------
// c[j], j = 256*j2 + j1; only j2 < 128 needed (j < T). Re -> row 2p, Im -> 2p+1.
__global__ void __launch_bounds__(256) k_inv_cols(float* __restrict__ y) {
    extern __shared__ float2 smem[];
    float2* bufA = smem; float2* bufB = smem + BUFSZ; float2* tw = smem + 2*BUFSZ;
    init_twiddles(tw);
    const int tid  = threadIdx.x;
    const int tile = blockIdx.x;
    const int pr   = blockIdx.y;
    const float2* g = g_G + (size_t)pr * NFFT;
    const int c     = tid & (NC-1);
    const int j1    = tile*NC + c;
    const int rbase = tid >> 4;
#pragma unroll
    for (int it = 0; it < 16; ++it) {
        int k1 = rbase + 16*it;
        bufA[k1*PAD + c] = g[k1*256 + j1];
    }
    fft256<1>(bufA, bufB, tw);
    const float scale = 1.0f / (float)NFFT;
    float* y0 = y + (size_t)(2*pr)*T_LEN;
    float* y1 = y0 + T_LEN;
#pragma unroll
    for (int it = 0; it < 8; ++it) {
        int j2 = rbase + 16*it;           // 0..127
        float2 v = bufA[j2*PAD + c];
        int j = j1 + 256*j2;
        y0[j] = v.x * scale;
        y1[j] = v.y * scale;
    }
}

extern "C" void kernel_launch(void* const* d_in, const int* in_sizes, int n_in,
                              void* d_out, int out_size) {
    const float* x   = (const float*)d_in[0];
    const float* flt = (const float*)d_in[1];
    float* y = (float*)d_out;
    int B = in_sizes[0] / T_LEN;     // 256
    int npairs = B / 2;              // 128

    cudaFuncSetAttribute(k_fwd_cols_batch, cudaFuncAttributeMaxDynamicSharedMemorySize, SMEM_BYTES);
    cudaFuncSetAttribute(k_fwd_cols_filt,  cudaFuncAttributeMaxDynamicSharedMemorySize, SMEM_BYTES);
    cudaFuncSetAttribute(k_rows_filt,      cudaFuncAttributeMaxDynamicSharedMemorySize, SMEM_BYTES);
    cudaFuncSetAttribute(k_rows_conv,      cudaFuncAttributeMaxDynamicSharedMemorySize, SMEM_BYTES);
    cudaFuncSetAttribute(k_inv_cols,       cudaFuncAttributeMaxDynamicSharedMemorySize, SMEM_BYTES);

    dim3 blk(256);
    // filter spectrum (tiny: 16 CTAs each)
    k_fwd_cols_filt<<<dim3(16, 1), blk, SMEM_BYTES>>>(flt);
    k_rows_filt   <<<dim3(16, 1), blk, SMEM_BYTES>>>();
    // main pipeline
    k_fwd_cols_batch<<<dim3(16, npairs), blk, SMEM_BYTES>>>(x);
    k_rows_conv     <<<dim3(16, npairs), blk, SMEM_BYTES>>>();
    k_inv_cols      <<<dim3(16, npairs), blk, SMEM_BYTES>>>(y);
}

// round 3
// speedup vs baseline: 1.6177x; 1.6177x over previous
#include <cuda_runtime.h>
#include <math.h>

// EpochedFutureFill: y[b,t] = sum_s filt[s] * x[b,t-s] via 65536-pt FFT conv.
// 65536 = 256 x 256 four-step. Row pairs packed as complex (Hermitian filter
// spectrum commutes with the packing). Each 256-pt FFT = two register-resident
// 16-pt FFTs with ONE smem transpose between them (radix-4^2 in registers).

#define T_LEN 32768
#define NFFT  65536
#define NPAIRS 128
#define PI_F 3.14159265358979323846f

__device__ float2 g_G[(size_t)NPAIRS * NFFT];   // 64MB scratch (P2 in-place)
__device__ float2 g_Gf[NFFT];                   // filter intermediate
__device__ float2 g_Wp[NFFT];                   // filter spectrum, permuted layout

__device__ __forceinline__ float2 cmul(float2 a, float2 b) {
    return make_float2(a.x*b.x - a.y*b.y, a.x*b.y + a.y*b.x);
}
__device__ __forceinline__ float2 cadd(float2 a, float2 b){ return make_float2(a.x+b.x, a.y+b.y); }
__device__ __forceinline__ float2 csub(float2 a, float2 b){ return make_float2(a.x-b.x, a.y-b.y); }

// 16-pt FFT leaves output index PERM(slot) in slot (base-4 digit swap; involution).
#define PERM(s) ((((s)&3)<<2) | ((s)>>2))

template<int SIGN>
__device__ __forceinline__ void bf4(float2&a, float2&b, float2&c, float2&d){
    float2 apc = cadd(a,c), amc = csub(a,c);
    float2 bpd = cadd(b,d), bmd = csub(b,d);
    float2 y1, y3;
    if (SIGN < 0){
        y1 = make_float2(amc.x + bmd.y, amc.y - bmd.x);
        y3 = make_float2(amc.x - bmd.y, amc.y + bmd.x);
    } else {
        y1 = make_float2(amc.x - bmd.y, amc.y + bmd.x);
        y3 = make_float2(amc.x + bmd.y, amc.y - bmd.x);
    }
    a = cadd(apc, bpd); b = y1; c = csub(apc, bpd); d = y3;
}

template<int SIGN>
__device__ __forceinline__ float2 mulw(float2 a, float cr, float si){
    float wi = (SIGN < 0) ? -si : si;
    return make_float2(a.x*cr - a.y*wi, a.x*wi + a.y*cr);
}

template<int SIGN>
__device__ __forceinline__ void fft16(float2 v[16]){
    // stage 1: DFT4 over the stride-4 classes; B[n1][m] lands in slot n1+4m
    bf4<SIGN>(v[0], v[4], v[8],  v[12]);
    bf4<SIGN>(v[1], v[5], v[9],  v[13]);
    bf4<SIGN>(v[2], v[6], v[10], v[14]);
    bf4<SIGN>(v[3], v[7], v[11], v[15]);
    const float C1 = 0.923879532511287f, S1 = 0.382683432365090f, C2 = 0.707106781186548f;
    // twiddle w16^{n1*m} at slot n1+4m
    v[5]  = mulw<SIGN>(v[5],  C1,  S1);   // t=1
    v[9]  = mulw<SIGN>(v[9],  C2,  C2);   // t=2
    v[13] = mulw<SIGN>(v[13], S1,  C1);   // t=3
    v[6]  = mulw<SIGN>(v[6],  C2,  C2);   // t=2
    v[10] = (SIGN<0) ? make_float2(v[10].y, -v[10].x)
                     : make_float2(-v[10].y, v[10].x);   // t=4 (∓i)
    v[14] = mulw<SIGN>(v[14], -C2, C2);   // t=6
    v[7]  = mulw<SIGN>(v[7],  S1,  C1);   // t=3
    v[11] = mulw<SIGN>(v[11], -C2, C2);   // t=6
    v[15] = mulw<SIGN>(v[15], -C1, -S1);  // t=9
    // stage 2: DFT4 over n1 per m; X[m+4k2] lands in slot k2+4m = PERM(m+4k2)
    bf4<SIGN>(v[0],  v[1],  v[2],  v[3]);
    bf4<SIGN>(v[4],  v[5],  v[6],  v[7]);
    bf4<SIGN>(v[8],  v[9],  v[10], v[11]);
    bf4<SIGN>(v[12], v[13], v[14], v[15]);
}

// 256-pt FFT: thread r (of 16) holds f[16*i + r] in v[i], for column `col`.
// Result: X[r + 16*k2] in v[PERM(k2)].  One smem transpose.
template<int SIGN, bool PRESYNC>
__device__ __forceinline__ void fft256_reg(float2 v[16], float* sre, float* sim,
                                           int col, int r){
    fft16<SIGN>(v);
    float s0, c0;
    sincosf((float)SIGN * (2.0f*PI_F/256.0f) * (float)r, &s0, &c0);
    float2 stp = make_float2(c0, s0);
    float2 f = make_float2(1.f, 0.f);
    if (PRESYNC) __syncthreads();
#pragma unroll
    for (int k1 = 0; k1 < 16; ++k1){
        float2 t = cmul(v[PERM(k1)], f);   // A[r][k1] * w256^{r*k1}
        int a = (k1*16 + r)*17 + col;
        sre[a] = t.x; sim[a] = t.y;
        f = cmul(f, stp);
    }
    __syncthreads();
#pragma unroll
    for (int n2 = 0; n2 < 16; ++n2){
        int a = (r*16 + n2)*17 + col;
        v[n2] = make_float2(sre[a], sim[a]);
    }
    fft16<SIGN>(v);
}

// ---------------- Pass 1: forward column FFTs + outer twiddle -----------------
__global__ void __launch_bounds__(256) k_fwd_cols_batch(const float* __restrict__ x){
    __shared__ float sre[4352], sim[4352];
    const int tid = threadIdx.x, col = tid & 15, r = tid >> 4;
    const int tile = blockIdx.x, pr = blockIdx.y;
    const int j2 = tile*16 + col;
    const float* x0 = x + (size_t)(2*pr)*T_LEN;
    const float* x1 = x0 + T_LEN;
    float2 v[16];
#pragma unroll
    for (int n1 = 0; n1 < 16; ++n1){
        if (n1 < 8){
            int j = (16*n1 + r)*256 + j2;
            v[n1] = make_float2(x0[j], x1[j]);
        } else v[n1] = make_float2(0.f, 0.f);
    }
    fft256_reg<-1,false>(v, sre, sim, col, r);
    float2* g = g_G + (size_t)pr*NFFT;
    float s0,c0,s1,c1;
    sincosf(-(2.0f*PI_F/65536.0f)*(float)(j2*r),  &s0,&c0);
    sincosf(-(2.0f*PI_F/65536.0f)*(float)(j2*16), &s1,&c1);
    float2 f = make_float2(c0,s0), stp = make_float2(c1,s1);
#pragma unroll
    for (int k2 = 0; k2 < 16; ++k2){
        int k1 = r + 16*k2;
        g[k1*256 + j2] = cmul(v[PERM(k2)], f);
        f = cmul(f, stp);
    }
}

__global__ void __launch_bounds__(256) k_fwd_cols_filt(const float* __restrict__ flt){
    __shared__ float sre[4352], sim[4352];
    const int tid = threadIdx.x, col = tid & 15, r = tid >> 4;
    const int tile = blockIdx.x;
    const int j2 = tile*16 + col;
    float2 v[16];
#pragma unroll
    for (int n1 = 0; n1 < 16; ++n1){
        if (n1 < 8){
            int j = (16*n1 + r)*256 + j2;
            v[n1] = make_float2(flt[j], 0.f);
        } else v[n1] = make_float2(0.f, 0.f);
    }
    fft256_reg<-1,false>(v, sre, sim, col, r);
    float s0,c0,s1,c1;
    sincosf(-(2.0f*PI_F/65536.0f)*(float)(j2*r),  &s0,&c0);
    sincosf(-(2.0f*PI_F/65536.0f)*(float)(j2*16), &s1,&c1);
    float2 f = make_float2(c0,s0), stp = make_float2(c1,s1);
#pragma unroll
    for (int k2 = 0; k2 < 16; ++k2){
        int k1 = r + 16*k2;
        g_Gf[k1*256 + j2] = cmul(v[PERM(k2)], f);
        f = cmul(f, stp);
    }
}

// ----------- Filter pass 2: row FFTs -> spectrum in permuted layout -----------
__global__ void __launch_bounds__(256) k_rows_filt(){
    __shared__ float sre[4352], sim[4352];
    const int tid = threadIdx.x, col = tid & 15, r = tid >> 4;
    const int tile = blockIdx.x;
#pragma unroll
    for (int it = 0; it < 16; ++it){
        float2 t = g_Gf[(tile*16 + it)*256 + tid];
        sre[tid*17 + it] = t.x; sim[tid*17 + it] = t.y;
    }
    __syncthreads();
    float2 v[16];
#pragma unroll
    for (int n1 = 0; n1 < 16; ++n1){
        int a = (16*n1 + r)*17 + col;
        v[n1] = make_float2(sre[a], sim[a]);
    }
    fft256_reg<-1,true>(v, sre, sim, col, r);
    // v[PERM(k2)] = W[row = tile*16+col][k2full = r + 16*k2]
#pragma unroll
    for (int k2 = 0; k2 < 16; ++k2)
        g_Wp[((tile*16 + k2)*16 + r)*16 + col] = v[PERM(k2)];
}

// ------ Pass 2: finish forward, multiply W, start inverse (in place) ----------
__global__ void __launch_bounds__(256) k_rows_conv(){
    __shared__ float sre[4352], sim[4352];
    const int tid = threadIdx.x, col = tid & 15, r = tid >> 4;
    const int tile = blockIdx.x;
    float2* g = g_G + (size_t)blockIdx.y * NFFT;
#pragma unroll
    for (int it = 0; it < 16; ++it){
        float2 t = g[(tile*16 + it)*256 + tid];
        sre[tid*17 + it] = t.x; sim[tid*17 + it] = t.y;
    }
    __syncthreads();
    float2 v[16];
#pragma unroll
    for (int n1 = 0; n1 < 16; ++n1){
        int a = (16*n1 + r)*17 + col;
        v[n1] = make_float2(sre[a], sim[a]);
    }
    fft256_reg<-1,true>(v, sre, sim, col, r);   // Z[row][r+16k2] in v[PERM(k2)]
    // Multiply by W AND undo the output slot permutation: u[k2] = P[16*k2 + r],
    // which is exactly fft256_reg's input convention (f[16*i + r] in slot i).
    float2 u[16];
#pragma unroll
    for (int k2 = 0; k2 < 16; ++k2){
        float2 w = g_Wp[((tile*16 + k2)*16 + r)*16 + col];
        u[k2] = cmul(v[PERM(k2)], w);
    }
    fft256_reg<1,true>(u, sre, sim, col, r);    // D[jj = r + 16*b] in u[PERM(b)]
    // inverse outer twiddle exp(+2pi i * k1row * jj / 65536)
    const int k1row = tile*16 + col;
    float s0,c0,s1,c1;
    sincosf((2.0f*PI_F/65536.0f)*(float)(k1row*r),  &s0,&c0);
    sincosf((2.0f*PI_F/65536.0f)*(float)(k1row*16), &s1,&c1);
    float2 f = make_float2(c0,s0), stp = make_float2(c1,s1);
    __syncthreads();                            // smem free after exchange read
#pragma unroll
    for (int b = 0; b < 16; ++b){
        int jj = r + 16*b;
        float2 t = cmul(u[PERM(b)], f);
        sre[jj*17 + col] = t.x; sim[jj*17 + col] = t.y;
        f = cmul(f, stp);
    }
    __syncthreads();
#pragma unroll
    for (int it = 0; it < 16; ++it)
        g[(tile*16 + it)*256 + tid] = make_float2(sre[tid*17 + it], sim[tid*17 + it]);
}

// ---------------- Pass 3: inverse column FFTs + output ------------------------
__global__ void __launch_bounds__(256) k_inv_cols(float* __restrict__ y){
    __shared__ float sre[4352], sim[4352];
    const int tid = threadIdx.x, col = tid & 15, r = tid >> 4;
    const int tile = blockIdx.x, pr = blockIdx.y;
    const int j1 = tile*16 + col;
    const float2* g = g_G + (size_t)pr * NFFT;
    float2 v[16];
#pragma unroll
    for (int n1 = 0; n1 < 16; ++n1)
        v[n1] = g[(16*n1 + r)*256 + j1];
    fft256_reg<1,false>(v, sre, sim, col, r);
    const float sc = 1.0f / (float)NFFT;
    float* y0 = y + (size_t)(2*pr)*T_LEN;
    float* y1 = y0 + T_LEN;
#pragma unroll
    for (int k2 = 0; k2 < 8; ++k2){             // j2o = r+16*k2 < 128 only
        int j2o = r + 16*k2;
        float2 t = v[PERM(k2)];
        int j = j2o*256 + j1;
        y0[j] = t.x * sc;
        y1[j] = t.y * sc;
    }
}

extern "C" void kernel_launch(void* const* d_in, const int* in_sizes, int n_in,
                              void* d_out, int out_size) {
    const float* x   = (const float*)d_in[0];
    const float* flt = (const float*)d_in[1];
    float* y = (float*)d_out;
    int B = in_sizes[0] / T_LEN;     // 256
    int npairs = B / 2;              // 128

    dim3 blk(256);
    k_fwd_cols_filt<<<dim3(16, 1), blk>>>(flt);
    k_rows_filt    <<<dim3(16, 1), blk>>>();
    k_fwd_cols_batch<<<dim3(16, npairs), blk>>>(x);
    k_rows_conv     <<<dim3(16, npairs), blk>>>();
    k_inv_cols      <<<dim3(16, npairs), blk>>>(y);
}

// round 4
// speedup vs baseline: 1.7296x; 1.0692x over previous
#include <cuda_runtime.h>
#include <math.h>

// EpochedFutureFill: y[b,t] = sum_s filt[s] * x[b,t-s] via 65536-pt FFT conv.
// 65536 = 256 x 256 four-step; row pairs packed as complex.
// g_G chunk layout: addr(k1,j2) = pr*65536 + (k1>>4)*4096 + (j2>>4)*256
//                                 + (k1&15)*16 + (j2&15)
// -> every pass reads/writes global with offset == tid (fully coalesced), and
//    only the intra-256-FFT transposes touch shared memory.

#define T_LEN 32768
#define NFFT  65536
#define NPAIRS 128
#define PI_F 3.14159265358979323846f

__device__ float2 g_G[(size_t)NPAIRS * NFFT];   // 64MB scratch (P2 in-place)
__device__ float2 g_Gf[NFFT];                   // filter intermediate (chunk layout)
__device__ float2 g_Wp[NFFT];                   // filter spectrum (chunk layout)

__device__ __forceinline__ float2 cmul(float2 a, float2 b) {
    return make_float2(a.x*b.x - a.y*b.y, a.x*b.y + a.y*b.x);
}
__device__ __forceinline__ float2 cadd(float2 a, float2 b){ return make_float2(a.x+b.x, a.y+b.y); }
__device__ __forceinline__ float2 csub(float2 a, float2 b){ return make_float2(a.x-b.x, a.y-b.y); }

// 16-pt FFT leaves output index PERM(slot) in slot (base-4 digit swap; involution).
#define PERM(s) ((((s)&3)<<2) | ((s)>>2))

template<int SIGN>
__device__ __forceinline__ void bf4(float2&a, float2&b, float2&c, float2&d){
    float2 apc = cadd(a,c), amc = csub(a,c);
    float2 bpd = cadd(b,d), bmd = csub(b,d);
    float2 y1, y3;
    if (SIGN < 0){
        y1 = make_float2(amc.x + bmd.y, amc.y - bmd.x);
        y3 = make_float2(amc.x - bmd.y, amc.y + bmd.x);
    } else {
        y1 = make_float2(amc.x - bmd.y, amc.y + bmd.x);
        y3 = make_float2(amc.x + bmd.y, amc.y - bmd.x);
    }
    a = cadd(apc, bpd); b = y1; c = csub(apc, bpd); d = y3;
}

template<int SIGN>
__device__ __forceinline__ float2 mulw(float2 a, float cr, float si){
    float wi = (SIGN < 0) ? -si : si;
    return make_float2(a.x*cr - a.y*wi, a.x*wi + a.y*cr);
}

template<int SIGN>
__device__ __forceinline__ void fft16(float2 v[16]){
    bf4<SIGN>(v[0], v[4], v[8],  v[12]);
    bf4<SIGN>(v[1], v[5], v[9],  v[13]);
    bf4<SIGN>(v[2], v[6], v[10], v[14]);
    bf4<SIGN>(v[3], v[7], v[11], v[15]);
    const float C1 = 0.923879532511287f, S1 = 0.382683432365090f, C2 = 0.707106781186548f;
    v[5]  = mulw<SIGN>(v[5],  C1,  S1);
    v[9]  = mulw<SIGN>(v[9],  C2,  C2);
    v[13] = mulw<SIGN>(v[13], S1,  C1);
    v[6]  = mulw<SIGN>(v[6],  C2,  C2);
    v[10] = (SIGN<0) ? make_float2(v[10].y, -v[10].x)
                     : make_float2(-v[10].y, v[10].x);
    v[14] = mulw<SIGN>(v[14], -C2, C2);
    v[7]  = mulw<SIGN>(v[7],  S1,  C1);
    v[11] = mulw<SIGN>(v[11], -C2, C2);
    v[15] = mulw<SIGN>(v[15], -C1, -S1);
    bf4<SIGN>(v[0],  v[1],  v[2],  v[3]);
    bf4<SIGN>(v[4],  v[5],  v[6],  v[7]);
    bf4<SIGN>(v[8],  v[9],  v[10], v[11]);
    bf4<SIGN>(v[12], v[13], v[14], v[15]);
}

// Transpose smem addressing. LAYB=false: roles (col=tid&15, r=tid>>4), pad-17.
// LAYB=true: roles (col=tid>>4, r=tid&15), XOR-swizzled (bank-clean for both).
template<bool LAYB>
__device__ __forceinline__ int taddr(int p, int col){
    return LAYB ? (col*272 + (p ^ (p>>4))) : (p*17 + col);
}

// 256-pt FFT: thread r (of 16) holds f[16*i + r] in v[i], for column `col`.
// Result: X[r + 16*k2] in v[PERM(k2)].  One smem transpose.
template<int SIGN, bool PRESYNC, bool LAYB>
__device__ __forceinline__ void fft256_reg(float2 v[16], float2* buf, int col, int r){
    fft16<SIGN>(v);
    float s0, c0;
    sincosf((float)SIGN * (2.0f*PI_F/256.0f) * (float)r, &s0, &c0);
    float2 stp = make_float2(c0, s0);
    float2 f = make_float2(1.f, 0.f);
    if (PRESYNC) __syncthreads();
#pragma unroll
    for (int k1 = 0; k1 < 16; ++k1){
        float2 t = cmul(v[PERM(k1)], f);   // A[r][k1] * w256^{r*k1}
        buf[taddr<LAYB>(k1*16 + r, col)] = t;
        f = cmul(f, stp);
    }
    __syncthreads();
#pragma unroll
    for (int n2 = 0; n2 < 16; ++n2)
        v[n2] = buf[taddr<LAYB>(r*16 + n2, col)];
    fft16<SIGN>(v);
}

// ---------------- Pass 1: forward column FFTs + outer twiddle -----------------
__global__ void __launch_bounds__(256) k_fwd_cols_batch(const float* __restrict__ x){
    __shared__ float2 buf[4352];
    const int tid = threadIdx.x, col = tid & 15, r = tid >> 4;
    const int tile = blockIdx.x, pr = blockIdx.y;
    const int j2 = tile*16 + col;
    const float* x0 = x + (size_t)(2*pr)*T_LEN;
    const float* x1 = x0 + T_LEN;
    float2 v[16];
#pragma unroll
    for (int n1 = 0; n1 < 16; ++n1){
        if (n1 < 8){
            int j = (16*n1 + r)*256 + j2;
            v[n1] = make_float2(x0[j], x1[j]);
        } else v[n1] = make_float2(0.f, 0.f);
    }
    fft256_reg<-1,false,false>(v, buf, col, r);
    float2* g = g_G + (size_t)pr*NFFT;
    float s0,c0,s1,c1;
    sincosf(-(2.0f*PI_F/65536.0f)*(float)(j2*r),  &s0,&c0);
    sincosf(-(2.0f*PI_F/65536.0f)*(float)(j2*16), &s1,&c1);
    float2 f = make_float2(c0,s0), stp = make_float2(c1,s1);
#pragma unroll
    for (int k2 = 0; k2 < 16; ++k2){
        // k1 = r + 16*k2 -> chunk (k2, tile), offset tid
        g[k2*4096 + tile*256 + tid] = cmul(v[PERM(k2)], f);
        f = cmul(f, stp);
    }
}

__global__ void __launch_bounds__(256) k_fwd_cols_filt(const float* __restrict__ flt){
    __shared__ float2 buf[4352];
    const int tid = threadIdx.x, col = tid & 15, r = tid >> 4;
    const int tile = blockIdx.x;
    const int j2 = tile*16 + col;
    float2 v[16];
#pragma unroll
    for (int n1 = 0; n1 < 16; ++n1){
        if (n1 < 8){
            int j = (16*n1 + r)*256 + j2;
            v[n1] = make_float2(flt[j], 0.f);
        } else v[n1] = make_float2(0.f, 0.f);
    }
    fft256_reg<-1,false,false>(v, buf, col, r);
    float s0,c0,s1,c1;
    sincosf(-(2.0f*PI_F/65536.0f)*(float)(j2*r),  &s0,&c0);
    sincosf(-(2.0f*PI_F/65536.0f)*(float)(j2*16), &s1,&c1);
    float2 f = make_float2(c0,s0), stp = make_float2(c1,s1);
#pragma unroll
    for (int k2 = 0; k2 < 16; ++k2){
        g_Gf[k2*4096 + tile*256 + tid] = cmul(v[PERM(k2)], f);
        f = cmul(f, stp);
    }
}

// ----------- Filter pass 2: row FFTs -> spectrum in chunk layout --------------
__global__ void __launch_bounds__(256) k_rows_filt(){
    __shared__ float2 buf[4352];
    const int tid = threadIdx.x, col = tid >> 4, r = tid & 15;   // swapped roles
    const int tile = blockIdx.x;
    float2 v[16];
#pragma unroll
    for (int i = 0; i < 16; ++i)
        v[i] = g_Gf[tile*4096 + i*256 + tid];   // W-row tile*16+col, j2=16i+r
    fft256_reg<-1,false,true>(v, buf, col, r);
    // v[PERM(k2)] = W[row][r + 16*k2] -> chunk (tile, k2), offset tid
#pragma unroll
    for (int k2 = 0; k2 < 16; ++k2)
        g_Wp[tile*4096 + k2*256 + tid] = v[PERM(k2)];
}

// ------ Pass 2: finish forward, multiply W, start inverse (in place) ----------
__global__ void __launch_bounds__(256) k_rows_conv(){
    __shared__ float2 buf[4352];
    const int tid = threadIdx.x, col = tid >> 4, r = tid & 15;   // swapped roles
    const int tile = blockIdx.x;
    float2* g = g_G + (size_t)blockIdx.y * NFFT;
    float2 v[16];
#pragma unroll
    for (int i = 0; i < 16; ++i)
        v[i] = g[tile*4096 + i*256 + tid];      // Z-row tile*16+col, j2=16i+r
    fft256_reg<-1,false,true>(v, buf, col, r);  // Z[row][r+16k2] in v[PERM(k2)]
    // multiply by W and undo slot permutation: u[k2] = P[16*k2 + r]
    float2 u[16];
#pragma unroll
    for (int k2 = 0; k2 < 16; ++k2){
        float2 w = g_Wp[tile*4096 + k2*256 + tid];
        u[k2] = cmul(v[PERM(k2)], w);
    }
    fft256_reg<1,true,true>(u, buf, col, r);    // D[jj = r+16b] in u[PERM(b)]
    // inverse outer twiddle exp(+2pi i * k1row * jj / 65536), direct store
    const int k1row = tile*16 + col;
    float s0,c0,s1,c1;
    sincosf((2.0f*PI_F/65536.0f)*(float)(k1row*r),  &s0,&c0);
    sincosf((2.0f*PI_F/65536.0f)*(float)(k1row*16), &s1,&c1);
    float2 f = make_float2(c0,s0), stp = make_float2(c1,s1);
#pragma unroll
    for (int b = 0; b < 16; ++b){
        g[tile*4096 + b*256 + tid] = cmul(u[PERM(b)], f);   // chunk (tile, b)
        f = cmul(f, stp);
    }
}

// ---------------- Pass 3: inverse column FFTs + output ------------------------
__global__ void __launch_bounds__(256) k_inv_cols(float* __restrict__ y){
    __shared__ float2 buf[4352];
    const int tid = threadIdx.x, col = tid & 15, r = tid >> 4;
    const int tile = blockIdx.x, pr = blockIdx.y;
    const int j1 = tile*16 + col;
    const float2* g = g_G + (size_t)pr * NFFT;
    float2 v[16];
#pragma unroll
    for (int n1 = 0; n1 < 16; ++n1)
        v[n1] = g[n1*4096 + tile*256 + tid];    // c[k1=16n1+r][j1], offset tid
    fft256_reg<1,false,false>(v, buf, col, r);
    const float sc = 1.0f / (float)NFFT;
    float* y0 = y + (size_t)(2*pr)*T_LEN;
    float* y1 = y0 + T_LEN;
#pragma unroll
    for (int k2 = 0; k2 < 8; ++k2){             // j2o = r+16*k2 < 128 only
        int j2o = r + 16*k2;
        float2 t = v[PERM(k2)];
        int j = j2o*256 + j1;
        y0[j] = t.x * sc;
        y1[j] = t.y * sc;
    }
}

extern "C" void kernel_launch(void* const* d_in, const int* in_sizes, int n_in,
                              void* d_out, int out_size) {
    const float* x   = (const float*)d_in[0];
    const float* flt = (const float*)d_in[1];
    float* y = (float*)d_out;
    int B = in_sizes[0] / T_LEN;     // 256
    int npairs = B / 2;              // 128

    dim3 blk(256);
    k_fwd_cols_filt<<<dim3(16, 1), blk>>>(flt);
    k_rows_filt    <<<dim3(16, 1), blk>>>();
    k_fwd_cols_batch<<<dim3(16, npairs), blk>>>(x);
    k_rows_conv     <<<dim3(16, npairs), blk>>>();
    k_inv_cols      <<<dim3(16, npairs), blk>>>(y);
}

// round 5
// speedup vs baseline: 1.7939x; 1.0372x over previous
#include <cuda_runtime.h>
#include <math.h>

// EpochedFutureFill: y[b,t] = sum_s filt[s] * x[b,t-s] via 65536-pt FFT conv.
// 65536 = 256 x 256 four-step; row pairs packed as complex.
// g_G chunk layout: addr(k1,j2) = pr*65536 + (k1>>4)*4096 + (j2>>4)*256
//                                 + (k1&15)*16 + (j2&15)
// -> every pass reads/writes global with offset == tid (fully coalesced); only
//    the intra-256-FFT transposes touch shared memory.

#define T_LEN 32768
#define NFFT  65536
#define NPAIRS 128
#define PI_F 3.14159265358979323846f

__device__ float2 g_G[(size_t)NPAIRS * NFFT];   // 64MB scratch (P2 in-place)
__device__ float2 g_Gf[NFFT];                   // filter intermediate (chunk layout)
__device__ float2 g_Wp[NFFT];                   // filter spectrum (chunk layout)

__device__ __forceinline__ float2 cmul(float2 a, float2 b) {
    return make_float2(a.x*b.x - a.y*b.y, a.x*b.y + a.y*b.x);
}
__device__ __forceinline__ float2 cadd(float2 a, float2 b){ return make_float2(a.x+b.x, a.y+b.y); }
__device__ __forceinline__ float2 csub(float2 a, float2 b){ return make_float2(a.x-b.x, a.y-b.y); }

// base-4 digit swap (involution); fft16 leaves output index PERM(s) in slot s.
#define PERM(s) ((((s)&3)<<2) | ((s)>>2))
__device__ __forceinline__ constexpr int pm(int i, bool P){
    return P ? (((i & 3) << 2) | (i >> 2)) : i;
}

template<int SIGN>
__device__ __forceinline__ void bf4(float2&a, float2&b, float2&c, float2&d){
    float2 apc = cadd(a,c), amc = csub(a,c);
    float2 bpd = cadd(b,d), bmd = csub(b,d);
    float2 y1, y3;
    if (SIGN < 0){
        y1 = make_float2(amc.x + bmd.y, amc.y - bmd.x);
        y3 = make_float2(amc.x - bmd.y, amc.y + bmd.x);
    } else {
        y1 = make_float2(amc.x - bmd.y, amc.y + bmd.x);
        y3 = make_float2(amc.x + bmd.y, amc.y - bmd.x);
    }
    a = cadd(apc, bpd); b = y1; c = csub(apc, bpd); d = y3;
}

template<int SIGN>
__device__ __forceinline__ float2 mulw(float2 a, float cr, float si){
    float wi = (SIGN < 0) ? -si : si;
    return make_float2(a.x*cr - a.y*wi, a.x*wi + a.y*cr);
}

// fft16 over a (possibly PERM-permuted) register view.
template<int SIGN, bool P>
__device__ __forceinline__ void fft16m(float2 v[16]){
    bf4<SIGN>(v[pm(0,P)], v[pm(4,P)], v[pm(8,P)],  v[pm(12,P)]);
    bf4<SIGN>(v[pm(1,P)], v[pm(5,P)], v[pm(9,P)],  v[pm(13,P)]);
    bf4<SIGN>(v[pm(2,P)], v[pm(6,P)], v[pm(10,P)], v[pm(14,P)]);
    bf4<SIGN>(v[pm(3,P)], v[pm(7,P)], v[pm(11,P)], v[pm(15,P)]);
    const float C1 = 0.923879532511287f, S1 = 0.382683432365090f, C2 = 0.707106781186548f;
    v[pm(5,P)]  = mulw<SIGN>(v[pm(5,P)],  C1,  S1);
    v[pm(9,P)]  = mulw<SIGN>(v[pm(9,P)],  C2,  C2);
    v[pm(13,P)] = mulw<SIGN>(v[pm(13,P)], S1,  C1);
    v[pm(6,P)]  = mulw<SIGN>(v[pm(6,P)],  C2,  C2);
    v[pm(10,P)] = (SIGN<0) ? make_float2(v[pm(10,P)].y, -v[pm(10,P)].x)
                           : make_float2(-v[pm(10,P)].y, v[pm(10,P)].x);
    v[pm(14,P)] = mulw<SIGN>(v[pm(14,P)], -C2, C2);
    v[pm(7,P)]  = mulw<SIGN>(v[pm(7,P)],  S1,  C1);
    v[pm(11,P)] = mulw<SIGN>(v[pm(11,P)], -C2, C2);
    v[pm(15,P)] = mulw<SIGN>(v[pm(15,P)], -C1, -S1);
    bf4<SIGN>(v[pm(0,P)],  v[pm(1,P)],  v[pm(2,P)],  v[pm(3,P)]);
    bf4<SIGN>(v[pm(4,P)],  v[pm(5,P)],  v[pm(6,P)],  v[pm(7,P)]);
    bf4<SIGN>(v[pm(8,P)],  v[pm(9,P)],  v[pm(10,P)], v[pm(11,P)]);
    bf4<SIGN>(v[pm(12,P)], v[pm(13,P)], v[pm(14,P)], v[pm(15,P)]);
}

// Transpose smem addressing. LAYB=false: roles (col=tid&15, r=tid>>4), pad-17.
// LAYB=true: roles (col=tid>>4, r=tid&15), XOR-swizzled (bank-clean for both).
template<bool LAYB>
__device__ __forceinline__ int taddr(int p, int col){
    return LAYB ? (col*272 + (p ^ (p>>4))) : (p*17 + col);
}

// 256-pt FFT. Input: logical slot i holds f[16*i + r] — physically v[i]
// (INPERM=false) or v[PERM(i)] (INPERM=true). Output: X[r+16*k2] in v[PERM(k2)]
// (physical, natural mapping). One smem transpose; two-chain twiddles.
template<int SIGN, bool PRESYNC, bool LAYB, bool INPERM>
__device__ __forceinline__ void fft256_reg(float2 v[16], float2* buf, int col, int r){
    fft16m<SIGN, INPERM>(v);
    float s0, c0;
    sincosf((float)SIGN * (2.0f*PI_F/256.0f) * (float)r, &s0, &c0);
    float2 stp  = make_float2(c0, s0);
    float2 stp2 = cmul(stp, stp);
    float2 fe = make_float2(1.f, 0.f), fo = stp;
    if (PRESYNC) __syncthreads();
#pragma unroll
    for (int k1 = 0; k1 < 16; ++k1){
        // logical slot PERM(k1) -> physical pm(PERM(k1), INPERM)
        float2 t = (k1 & 1) ? cmul(v[pm(PERM(k1), INPERM)], fo)
                            : cmul(v[pm(PERM(k1), INPERM)], fe);
        buf[taddr<LAYB>(k1*16 + r, col)] = t;
        if (k1 & 1) fo = cmul(fo, stp2); else fe = cmul(fe, stp2);
    }
    __syncthreads();
#pragma unroll
    for (int n2 = 0; n2 < 16; ++n2)
        v[n2] = buf[taddr<LAYB>(r*16 + n2, col)];
    fft16m<SIGN, false>(v);
}

// ---------------- Pass 1: forward column FFTs + outer twiddle -----------------
__global__ void __launch_bounds__(256, 3) k_fwd_cols_batch(const float* __restrict__ x){
    __shared__ float2 buf[4352];
    const int tid = threadIdx.x, col = tid & 15, r = tid >> 4;
    const int tile = blockIdx.x, pr = blockIdx.y;
    const int j2 = tile*16 + col;
    const float* x0 = x + (size_t)(2*pr)*T_LEN;
    const float* x1 = x0 + T_LEN;
    float2 v[16];
#pragma unroll
    for (int n1 = 0; n1 < 16; ++n1){
        if (n1 < 8){
            int j = (16*n1 + r)*256 + j2;
            v[n1] = make_float2(x0[j], x1[j]);
        } else v[n1] = make_float2(0.f, 0.f);
    }
    fft256_reg<-1,false,false,false>(v, buf, col, r);
    float2* g = g_G + (size_t)pr*NFFT;
    float s0,c0,s1,c1;
    sincosf(-(2.0f*PI_F/65536.0f)*(float)(j2*r),  &s0,&c0);
    sincosf(-(2.0f*PI_F/65536.0f)*(float)(j2*32), &s1,&c1);
    float2 f0 = make_float2(c0,s0), stp2 = make_float2(c1,s1);
    sincosf(-(2.0f*PI_F/65536.0f)*(float)(j2*16), &s1,&c1);
    float2 f1 = cmul(f0, make_float2(c1,s1));
#pragma unroll
    for (int k2 = 0; k2 < 16; ++k2){
        // k1 = r + 16*k2 -> chunk (k2, tile), offset tid
        float2 t = (k2 & 1) ? cmul(v[PERM(k2)], f1) : cmul(v[PERM(k2)], f0);
        g[k2*4096 + tile*256 + tid] = t;
        if (k2 & 1) f1 = cmul(f1, stp2); else f0 = cmul(f0, stp2);
    }
}

__global__ void __launch_bounds__(256) k_fwd_cols_filt(const float* __restrict__ flt){
    __shared__ float2 buf[4352];
    const int tid = threadIdx.x, col = tid & 15, r = tid >> 4;
    const int tile = blockIdx.x;
    const int j2 = tile*16 + col;
    float2 v[16];
#pragma unroll
    for (int n1 = 0; n1 < 16; ++n1){
        if (n1 < 8){
            int j = (16*n1 + r)*256 + j2;
            v[n1] = make_float2(flt[j], 0.f);
        } else v[n1] = make_float2(0.f, 0.f);
    }
    fft256_reg<-1,false,false,false>(v, buf, col, r);
    float s0,c0,s1,c1;
    sincosf(-(2.0f*PI_F/65536.0f)*(float)(j2*r),  &s0,&c0);
    sincosf(-(2.0f*PI_F/65536.0f)*(float)(j2*16), &s1,&c1);
    float2 f = make_float2(c0,s0), stp = make_float2(c1,s1);
#pragma unroll
    for (int k2 = 0; k2 < 16; ++k2){
        g_Gf[k2*4096 + tile*256 + tid] = cmul(v[PERM(k2)], f);
        f = cmul(f, stp);
    }
}

// ----------- Filter pass 2: row FFTs -> spectrum in chunk layout --------------
__global__ void __launch_bounds__(256) k_rows_filt(){
    __shared__ float2 buf[4352];
    const int tid = threadIdx.x, col = tid >> 4, r = tid & 15;   // swapped roles
    const int tile = blockIdx.x;
    float2 v[16];
#pragma unroll
    for (int i = 0; i < 16; ++i)
        v[i] = g_Gf[tile*4096 + i*256 + tid];   // W-row tile*16+col, j2=16i+r
    fft256_reg<-1,false,true,false>(v, buf, col, r);
    // v[PERM(k2)] = W[row][r + 16*k2] -> chunk (tile, k2), offset tid
#pragma unroll
    for (int k2 = 0; k2 < 16; ++k2)
        g_Wp[tile*4096 + k2*256 + tid] = v[PERM(k2)];
}

// ------ Pass 2: finish forward, multiply W, start inverse (in place) ----------
__global__ void __launch_bounds__(256, 3) k_rows_conv(){
    __shared__ float2 buf[4352];
    const int tid = threadIdx.x, col = tid >> 4, r = tid & 15;   // swapped roles
    const int tile = blockIdx.x;
    float2* g = g_G + (size_t)blockIdx.y * NFFT;
    float2 v[16];
#pragma unroll
    for (int i = 0; i < 16; ++i)
        v[i] = g[tile*4096 + i*256 + tid];      // Z-row tile*16+col, j2=16i+r
    fft256_reg<-1,false,true,false>(v, buf, col, r);  // Z[row][r+16k2] in v[PERM(k2)]
    // multiply by W in place; logical slot k2 of the inverse input = v[PERM(k2)]
#pragma unroll
    for (int k2 = 0; k2 < 16; ++k2){
        float2 w = g_Wp[tile*4096 + k2*256 + tid];
        v[PERM(k2)] = cmul(v[PERM(k2)], w);
    }
    fft256_reg<1,true,true,true>(v, buf, col, r);     // D[jj=r+16b] in v[PERM(b)]
    // inverse outer twiddle exp(+2pi i * k1row * jj / 65536), two chains
    const int k1row = tile*16 + col;
    float s0,c0,s1,c1;
    sincosf((2.0f*PI_F/65536.0f)*(float)(k1row*r),  &s0,&c0);
    sincosf((2.0f*PI_F/65536.0f)*(float)(k1row*32), &s1,&c1);
    float2 f0 = make_float2(c0,s0), stp2 = make_float2(c1,s1);
    sincosf((2.0f*PI_F/65536.0f)*(float)(k1row*16), &s1,&c1);
    float2 f1 = cmul(f0, make_float2(c1,s1));
#pragma unroll
    for (int b = 0; b < 16; ++b){
        float2 t = (b & 1) ? cmul(v[PERM(b)], f1) : cmul(v[PERM(b)], f0);
        g[tile*4096 + b*256 + tid] = t;         // chunk (tile, b), offset tid
        if (b & 1) f1 = cmul(f1, stp2); else f0 = cmul(f0, stp2);
    }
}

// ---------------- Pass 3: inverse column FFTs + output ------------------------
__global__ void __launch_bounds__(256, 3) k_inv_cols(float* __restrict__ y){
    __shared__ float2 buf[4352];
    const int tid = threadIdx.x, col = tid & 15, r = tid >> 4;
    const int tile = blockIdx.x, pr = blockIdx.y;
    const int j1 = tile*16 + col;
    const float2* g = g_G + (size_t)pr * NFFT;
    float2 v[16];
#pragma unroll
    for (int n1 = 0; n1 < 16; ++n1)
        v[n1] = g[n1*4096 + tile*256 + tid];    // c[k1=16n1+r][j1], offset tid
    fft256_reg<1,false,false,false>(v, buf, col, r);
    const float sc = 1.0f / (float)NFFT;
    float* y0 = y + (size_t)(2*pr)*T_LEN;
    float* y1 = y0 + T_LEN;
#pragma unroll
    for (int k2 = 0; k2 < 8; ++k2){             // j2o = r+16*k2 < 128 only
        int j2o = r + 16*k2;
        float2 t = v[PERM(k2)];
        int j = j2o*256 + j1;
        y0[j] = t.x * sc;
        y1[j] = t.y * sc;
    }
}

extern "C" void kernel_launch(void* const* d_in, const int* in_sizes, int n_in,
                              void* d_out, int out_size) {
    const float* x   = (const float*)d_in[0];
    const float* flt = (const float*)d_in[1];
    float* y = (float*)d_out;
    int B = in_sizes[0] / T_LEN;     // 256
    int npairs = B / 2;              // 128

    dim3 blk(256);
    k_fwd_cols_filt<<<dim3(16, 1), blk>>>(flt);
    k_rows_filt    <<<dim3(16, 1), blk>>>();
    k_fwd_cols_batch<<<dim3(16, npairs), blk>>>(x);
    k_rows_conv     <<<dim3(16, npairs), blk>>>();
    k_inv_cols      <<<dim3(16, npairs), blk>>>(y);
}